// round 4
// baseline (speedup 1.0000x reference)
#include <cuda_runtime.h>
#include <cuda_fp16.h>
#include <cstdint>

// APRConv1x1 as a stencil-scattered GEMM on HMMA (mma.sync m16n8k16):
//   x~[n, i*4+s(n)] = x[i,n]  (K=64 virtual channels, 16 nonzero)
//   out[n,:] = x~ @ W~^T + bias,  W~[o,k] = Wg[o*64+k]  (Wg layout as-is)
// Weights live in B-register fragments (loaded once) -> zero per-point weight
// traffic through the LDS crossbar (the R1/R2 wall). x~ staged per-warp in
// smem (SW128 swizzle, conflict-free STS.128 / ldmatrix). D stored directly
// from fragments: each STG.32 fills full 32B sectors -> no DRAM amplification.
// Bias folded into accumulator init.

#define THREADS 128   // 4 warps, 32 points per warp, 128 points per block

__device__ __forceinline__ unsigned swz(unsigned off) {
    return off ^ ((off >> 3) & 0x70);
}

__global__ __launch_bounds__(THREADS)
void apr_mma_kernel(const float* __restrict__ x,
                    const float* __restrict__ Wg,    // [16,16,4] = W~[16][64]
                    const float* __restrict__ bias,  // [16]
                    const int*   __restrict__ sidx,  // [P]
                    float* __restrict__ out,         // [B,16,N]
                    int Nn, int P)
{
    __shared__ __align__(1024) char stage_raw[4 * 4096];

    const int tid = threadIdx.x;
    const int wid = tid >> 5;
    const int l   = tid & 31;
    const unsigned stg_s = (unsigned)__cvta_generic_to_shared(stage_raw + wid * 4096);

    const int c  = l >> 2;   // 0..7
    const int tp = l & 3;    // 0..3

    // ---- B fragments (weights) + bias-initialized accumulators ----
    // mma B frag (16x8, col): lane holds col n=c, k rows {2tp,2tp+1} (b0), {+8,+9} (b1)
    unsigned bf[2][4][2];
    float dD[2][2][4];       // [st][nb][reg]
#pragma unroll
    for (int nb = 0; nb < 2; nb++) {
        const int o = nb * 8 + c;
#pragma unroll
        for (int ks = 0; ks < 4; ks++) {
            const int k0 = ks * 16 + 2 * tp;
            const float2 w0 = *reinterpret_cast<const float2*>(Wg + o * 64 + k0);
            const float2 w1 = *reinterpret_cast<const float2*>(Wg + o * 64 + k0 + 8);
            __half2 h0 = __floats2half2_rn(w0.x, w0.y);
            __half2 h1 = __floats2half2_rn(w1.x, w1.y);
            bf[nb][ks][0] = *reinterpret_cast<unsigned*>(&h0);
            bf[nb][ks][1] = *reinterpret_cast<unsigned*>(&h1);
        }
        // D frag cols for this lane: nb*8+2tp, +1 (same for both row-halves)
        const float b0 = __ldg(bias + nb * 8 + 2 * tp);
        const float b1 = __ldg(bias + nb * 8 + 2 * tp + 1);
#pragma unroll
        for (int st = 0; st < 2; st++) {
            dD[st][nb][0] = b0; dD[st][nb][1] = b1;
            dD[st][nb][2] = b0; dD[st][nb][3] = b1;
        }
    }

    // ---- per-point input: build sparse x~ row, stage to smem ----
    const long long pt  = (long long)blockIdx.x * THREADS + tid;
    const long long ptc = pt < P ? pt : (long long)P - 1;
    const int  b  = ptc >= Nn ? 1 : 0;
    const long long n = ptc - (long long)b * Nn;
    const long long xbase = (long long)b * 16 * Nn + n;

    const int s = sidx[ptc];
    const bool lo = (s < 2);
    const unsigned sh = (unsigned)(s & 1) << 4;

#pragma unroll
    for (int h = 0; h < 2; h++) {           // two 64B halves of the 128B row
        unsigned r[16];
#pragma unroll
        for (int m = 0; m < 8; m++) {
            const float v = x[xbase + (long long)(8 * h + m) * Nn];
            const unsigned hw = (unsigned)__half_as_ushort(__float2half(v)) << sh;
            r[2 * m]     = lo ? hw : 0u;
            r[2 * m + 1] = lo ? 0u : hw;
        }
#pragma unroll
        for (int cc = 0; cc < 4; cc++) {
            const unsigned addr = stg_s + swz((unsigned)l * 128 + (h * 4 + cc) * 16);
            asm volatile("st.shared.v4.b32 [%0], {%1,%2,%3,%4};"
                         :: "r"(addr), "r"(r[4 * cc]), "r"(r[4 * cc + 1]),
                            "r"(r[4 * cc + 2]), "r"(r[4 * cc + 3]));
        }
    }
    __syncwarp();

    // ---- 2 subtiles x 4 ksteps: ldmatrix + 2 mma each ----
    const int m4 = l >> 3;                  // matrix id 0..3
#pragma unroll
    for (int st = 0; st < 2; st++) {
#pragma unroll
        for (int ks = 0; ks < 4; ks++) {
            const unsigned row  = (unsigned)(st * 16 + (m4 & 1) * 8 + (l & 7));
            const unsigned addr = stg_s + swz(row * 128 + ks * 32 + (m4 >> 1) * 16);
            unsigned a0, a1, a2, a3;
            asm volatile("ldmatrix.sync.aligned.m8n8.x4.shared.b16 {%0,%1,%2,%3}, [%4];"
                         : "=r"(a0), "=r"(a1), "=r"(a2), "=r"(a3) : "r"(addr));
#pragma unroll
            for (int nb = 0; nb < 2; nb++) {
                asm volatile(
                    "mma.sync.aligned.m16n8k16.row.col.f32.f16.f16.f32 "
                    "{%0,%1,%2,%3}, {%4,%5,%6,%7}, {%8,%9}, {%0,%1,%2,%3};"
                    : "+f"(dD[st][nb][0]), "+f"(dD[st][nb][1]),
                      "+f"(dD[st][nb][2]), "+f"(dD[st][nb][3])
                    : "r"(a0), "r"(a1), "r"(a2), "r"(a3),
                      "r"(bf[nb][ks][0]), "r"(bf[nb][ks][1]));
            }
        }
    }

    // ---- epilogue: direct fragment stores (full 32B sectors per instr) ----
    // D elem (row, col): c0/c1 -> row st*16+c(+0), cols nb*8+2tp, +1; c2/c3 -> row +8
    const long long wtb = (long long)blockIdx.x * THREADS + wid * 32;  // warp tile base pt
    const long long nb0 = wtb - (long long)b * Nn;                     // tile base n (b uniform)
    float* outb = out + (long long)b * 16 * Nn;
    const bool full = (wtb + 31) < (long long)P;

#pragma unroll
    for (int st = 0; st < 2; st++) {
#pragma unroll
        for (int nb = 0; nb < 2; nb++) {
            const int col = nb * 8 + 2 * tp;
            const long long r0 = st * 16 + c;
            if (full) {
                outb[(long long)col * Nn       + nb0 + r0]     = dD[st][nb][0];
                outb[(long long)(col + 1) * Nn + nb0 + r0]     = dD[st][nb][1];
                outb[(long long)col * Nn       + nb0 + r0 + 8] = dD[st][nb][2];
                outb[(long long)(col + 1) * Nn + nb0 + r0 + 8] = dD[st][nb][3];
            } else {
                if (wtb + r0 < P) {
                    outb[(long long)col * Nn       + nb0 + r0] = dD[st][nb][0];
                    outb[(long long)(col + 1) * Nn + nb0 + r0] = dD[st][nb][1];
                }
                if (wtb + r0 + 8 < P) {
                    outb[(long long)col * Nn       + nb0 + r0 + 8] = dD[st][nb][2];
                    outb[(long long)(col + 1) * Nn + nb0 + r0 + 8] = dD[st][nb][3];
                }
            }
        }
    }
}

extern "C" void kernel_launch(void* const* d_in, const int* in_sizes, int n_in,
                              void* d_out, int out_size)
{
    const float* x    = (const float*)d_in[0];   // [B, 16, N]
    const float* Wg   = (const float*)d_in[1];   // [16, 16, 4, 1, 1]
    const float* bias = (const float*)d_in[2];   // [16]
    const int*   sidx = (const int*)d_in[3];     // [B, N]

    float* out = (float*)d_out;

    const int P  = in_sizes[3];   // B*N
    const int Nn = P / 2;         // B = 2

    const int blocks = (P + THREADS - 1) / THREADS;  // 128 points per block
    apr_mma_kernel<<<blocks, THREADS>>>(x, Wg, bias, sidx, out, Nn, P);
}

// round 5
// speedup vs baseline: 1.2007x; 1.2007x over previous
#include <cuda_runtime.h>
#include <cuda_fp16.h>
#include <cstdint>

// APRConv1x1 as TWO K=32 HMMA GEMMs + per-element select:
//   k = 2*i + (s&1);  GEMM_h uses W_h[o][2i+j] = Wg[o*64 + 4i + 2h + j]
//   out[n,o] = (s(n)>>1) ? D_hi : D_lo   (bias folded into both accum inits)
// outT form: D[o][n] = W_h @ x~^T, M=16(o), N=8(pts), K=32 (2 ksteps).
// - Weights live in A-register fragments, loaded ONCE per persistent CTA.
// - x~ staged 2KB/warp, slot-swizzled: conflict-free STS.128 + ldmatrix.
// - Epilogue: consecutive-n float2 stores straight from D frags (full sectors).

#define THREADS 128

__device__ __forceinline__ unsigned h2u(__half2 h) {
    return *reinterpret_cast<unsigned*>(&h);
}

__global__ __launch_bounds__(THREADS, 5)
void apr_mma2_kernel(const float* __restrict__ x,
                     const float* __restrict__ Wg,    // [16][16][4]
                     const float* __restrict__ bias,  // [16]
                     const int*   __restrict__ sidx,  // [P]
                     float* __restrict__ out,         // [B][16][N]
                     long long Nn, long long P)
{
    __shared__ __align__(128) char stage[4][2048];

    const int tid = threadIdx.x;
    const int wid = tid >> 5;
    const int l   = tid & 31;
    const int r   = l >> 2;    // o row 0..7
    const int t   = l & 3;     // k-pair / n-pair selector
    const unsigned sbase = (unsigned)__cvta_generic_to_shared(stage[wid]);

    // ---- once: A fragments (2 weight halves x 2 ksteps) + bias ----
    unsigned a[2][2][4];
#pragma unroll
    for (int h = 0; h < 2; h++)
#pragma unroll
        for (int ks = 0; ks < 2; ks++) {
            const int i0 = 8 * ks + t;      // a0/a1 input channel
            const int i1 = 8 * ks + 4 + t;  // a2/a3 input channel
            float2 w;
            w = *(const float2*)(Wg + r * 64 + i0 * 4 + 2 * h);
            a[h][ks][0] = h2u(__floats2half2_rn(w.x, w.y));
            w = *(const float2*)(Wg + (r + 8) * 64 + i0 * 4 + 2 * h);
            a[h][ks][1] = h2u(__floats2half2_rn(w.x, w.y));
            w = *(const float2*)(Wg + r * 64 + i1 * 4 + 2 * h);
            a[h][ks][2] = h2u(__floats2half2_rn(w.x, w.y));
            w = *(const float2*)(Wg + (r + 8) * 64 + i1 * 4 + 2 * h);
            a[h][ks][3] = h2u(__floats2half2_rn(w.x, w.y));
        }
    const float br0 = __ldg(bias + r);
    const float br8 = __ldg(bias + r + 8);

    const long long wtiles = (P + 31) >> 5;
    const long long wstep  = (long long)gridDim.x * 4;

    for (long long wt = (long long)blockIdx.x * 4 + wid; wt < wtiles; wt += wstep) {
        const long long wtb = wt << 5;

        // ---- load 16 channels of my point, pack into K=32 sparse row ----
        const long long pt  = wtb + l;
        const long long ptc = pt < P ? pt : P - 1;
        const int  b  = ptc >= Nn ? 1 : 0;
        const long long n = ptc - (long long)b * Nn;
        const float* xp = x + (long long)b * 16 * Nn + n;

        const int s  = sidx[ptc];
        const bool lo = (s & 1) == 0;
        const int  sb = (s >> 1) & 1;

        unsigned v[16];
#pragma unroll
        for (int i = 0; i < 16; i++) {
            const float xv = xp[(long long)i * Nn];
            v[i] = lo ? h2u(__floats2half2_rn(xv, 0.f))
                      : h2u(__floats2half2_rn(0.f, xv));
        }

        // ---- stage: 2 points per 128B row, slot-swizzled (conflict-free) ----
        // addr(pt, cc) = (pt>>1)*128 + (((2cc + (pt&1)) ^ (((pt>>1)&3)<<1)) * 16
#pragma unroll
        for (int cc = 0; cc < 4; cc++) {
            const unsigned slot = ((unsigned)(2 * cc + (l & 1))) ^ ((((unsigned)l >> 1) & 3u) << 1);
            const unsigned addr = sbase + (((unsigned)l >> 1) << 7) + (slot << 4);
            asm volatile("st.shared.v4.b32 [%0], {%1,%2,%3,%4};"
                         :: "r"(addr), "r"(v[4*cc]), "r"(v[4*cc+1]),
                            "r"(v[4*cc+2]), "r"(v[4*cc+3]));
        }
        __syncwarp();

        // ---- accumulators (bias pre-folded into BOTH halves) ----
        float dl[4][4], dh[4][4];
#pragma unroll
        for (int g = 0; g < 4; g++) {
            dl[g][0] = br0; dl[g][1] = br0; dl[g][2] = br8; dl[g][3] = br8;
            dh[g][0] = br0; dh[g][1] = br0; dh[g][2] = br8; dh[g][3] = br8;
        }

        // ---- 4 point-groups: ldmatrix.x4 (all 4 k-octets) + 4 mmas ----
#pragma unroll
        for (int g = 0; g < 4; g++) {
            const int tt  = l >> 3;              // which 16B k-octet
            const int ptv = 8 * g + (l & 7);     // staged point row
            const unsigned slot = ((unsigned)(2 * tt + (ptv & 1))) ^ ((((unsigned)ptv >> 1) & 3u) << 1);
            const unsigned addr = sbase + (((unsigned)ptv >> 1) << 7) + (slot << 4);
            unsigned b0, b1, b2, b3;
            asm volatile("ldmatrix.sync.aligned.m8n8.x4.shared.b16 {%0,%1,%2,%3}, [%4];"
                         : "=r"(b0), "=r"(b1), "=r"(b2), "=r"(b3) : "r"(addr));
#pragma unroll
            for (int h = 0; h < 2; h++) {
                float* d = h ? dh[g] : dl[g];
                asm volatile(
                    "mma.sync.aligned.m16n8k16.row.col.f32.f16.f16.f32 "
                    "{%0,%1,%2,%3}, {%4,%5,%6,%7}, {%8,%9}, {%0,%1,%2,%3};"
                    : "+f"(d[0]), "+f"(d[1]), "+f"(d[2]), "+f"(d[3])
                    : "r"(a[h][0][0]), "r"(a[h][0][1]), "r"(a[h][0][2]), "r"(a[h][0][3]),
                      "r"(b0), "r"(b1));
                asm volatile(
                    "mma.sync.aligned.m16n8k16.row.col.f32.f16.f16.f32 "
                    "{%0,%1,%2,%3}, {%4,%5,%6,%7}, {%8,%9}, {%0,%1,%2,%3};"
                    : "+f"(d[0]), "+f"(d[1]), "+f"(d[2]), "+f"(d[3])
                    : "r"(a[h][1][0]), "r"(a[h][1][1]), "r"(a[h][1][2]), "r"(a[h][1][3]),
                      "r"(b2), "r"(b3));
            }
        }
        __syncwarp();   // ldmatrix reads done before next iter's STS

        // ---- select by s>>1, store consecutive-n float2 pairs ----
#pragma unroll
        for (int g = 0; g < 4; g++) {
            const int src = 8 * g + 2 * t;
            const int sb0 = __shfl_sync(0xffffffffu, sb, src);
            const int sb1 = __shfl_sync(0xffffffffu, sb, src + 1);
            const float o0 = sb0 ? dh[g][0] : dl[g][0];
            const float o1 = sb1 ? dh[g][1] : dl[g][1];
            const float o2 = sb0 ? dh[g][2] : dl[g][2];
            const float o3 = sb1 ? dh[g][3] : dl[g][3];

            const long long ptg = wtb + src;
            if (ptg + 1 < P) {
                const int bb = ptg >= Nn ? 1 : 0;
                const long long nn = ptg - (long long)bb * Nn;
                float* ob = out + (long long)bb * 16 * Nn + nn;
                *reinterpret_cast<float2*>(ob + (long long)r * Nn)       = make_float2(o0, o1);
                *reinterpret_cast<float2*>(ob + (long long)(r + 8) * Nn) = make_float2(o2, o3);
            } else if (ptg < P) {
                const int bb = ptg >= Nn ? 1 : 0;
                const long long nn = ptg - (long long)bb * Nn;
                float* ob = out + (long long)bb * 16 * Nn + nn;
                ob[(long long)r * Nn]       = o0;
                ob[(long long)(r + 8) * Nn] = o2;
            }
        }
    }
}

extern "C" void kernel_launch(void* const* d_in, const int* in_sizes, int n_in,
                              void* d_out, int out_size)
{
    const float* x    = (const float*)d_in[0];   // [B, 16, N]
    const float* Wg   = (const float*)d_in[1];   // [16, 16, 4, 1, 1]
    const float* bias = (const float*)d_in[2];   // [16]
    const int*   sidx = (const int*)d_in[3];     // [B, N]

    float* out = (float*)d_out;

    const long long P  = in_sizes[3];   // B*N
    const long long Nn = P / 2;         // B = 2

    const long long wtiles = (P + 31) / 32;
    long long blk = (wtiles + 3) / 4;
    if (blk > 1480) blk = 1480;         // persistent: ~10 CTAs/SM target

    apr_mma2_kernel<<<(int)blk, THREADS>>>(x, Wg, bias, sidx, out, Nn, P);
}

// round 6
// speedup vs baseline: 1.3984x; 1.1647x over previous
#include <cuda_runtime.h>
#include <cuda_fp16.h>
#include <cstdint>

// APRConv1x1 as TWO K=32 HMMA GEMMs + per-element select (R5 core, proven):
//   k = 2*i + (s&1);  out[n,o] = (s>>1) ? D_hi[o,n] : D_lo[o,n]; bias in accum init.
// R6 deltas (R5 ncu: DRAM 55.6%, occ 29.3% -> latency-bound):
//   1) software pipeline: prefetch next tile's sidx + 16 x floats during compute
//   2) per-group epilogue frees 24 accumulator regs (pays for prefetch regs)
//   3) 32-bit unsigned element offsets (alu was 30.8%)

#define THREADS 128

__device__ __forceinline__ unsigned h2u(__half2 h) {
    return *reinterpret_cast<unsigned*>(&h);
}

__global__ __launch_bounds__(THREADS, 5)
void apr_mma3_kernel(const float* __restrict__ x,
                     const float* __restrict__ Wg,    // [16][16][4]
                     const float* __restrict__ bias,  // [16]
                     const int*   __restrict__ sidx,  // [P]
                     float* __restrict__ out,         // [B][16][N]
                     unsigned Nn, unsigned P)
{
    __shared__ __align__(128) char stage[4][2048];

    const int tid = threadIdx.x;
    const int wid = tid >> 5;
    const int l   = tid & 31;
    const int r   = l >> 2;    // o row 0..7
    const int t   = l & 3;
    const unsigned sbase = (unsigned)__cvta_generic_to_shared(stage[wid]);

    // ---- once per CTA: weight A-fragments + bias ----
    unsigned a[2][2][4];
#pragma unroll
    for (int h = 0; h < 2; h++)
#pragma unroll
        for (int ks = 0; ks < 2; ks++) {
            const int i0 = 8 * ks + t;
            const int i1 = 8 * ks + 4 + t;
            float2 w;
            w = *(const float2*)(Wg + r * 64 + i0 * 4 + 2 * h);
            a[h][ks][0] = h2u(__floats2half2_rn(w.x, w.y));
            w = *(const float2*)(Wg + (r + 8) * 64 + i0 * 4 + 2 * h);
            a[h][ks][1] = h2u(__floats2half2_rn(w.x, w.y));
            w = *(const float2*)(Wg + r * 64 + i1 * 4 + 2 * h);
            a[h][ks][2] = h2u(__floats2half2_rn(w.x, w.y));
            w = *(const float2*)(Wg + (r + 8) * 64 + i1 * 4 + 2 * h);
            a[h][ks][3] = h2u(__floats2half2_rn(w.x, w.y));
        }
    const float br0 = __ldg(bias + r);
    const float br8 = __ldg(bias + r + 8);

    const unsigned wtiles = (P + 31) >> 5;
    const unsigned wstep  = (unsigned)gridDim.x * 4;

    unsigned wt = (unsigned)blockIdx.x * 4 + wid;
    if (wt >= wtiles) return;

    // ---- prologue: load tile 0 ----
    float fv[16];
    int   s_cur;
    {
        const unsigned pt  = wt * 32 + l;
        const unsigned ptc = pt < P ? pt : P - 1;
        const unsigned b   = ptc >= Nn ? 1u : 0u;
        const unsigned n   = ptc - b * Nn;
        const float* xp = x + (b * 16 * Nn + n);
        s_cur = sidx[ptc];
#pragma unroll
        for (int i = 0; i < 16; i++) fv[i] = xp[i * Nn];
    }

    for (; wt < wtiles; ) {
        const unsigned wtb = wt * 32;
        const unsigned wt_next = wt + wstep;

        // ---- prefetch next tile (overlaps everything below) ----
        float fn[16];
        int   s_next = 0;
        if (wt_next < wtiles) {
            const unsigned pt  = wt_next * 32 + l;
            const unsigned ptc = pt < P ? pt : P - 1;
            const unsigned b   = ptc >= Nn ? 1u : 0u;
            const unsigned n   = ptc - b * Nn;
            const float* xp = x + (b * 16 * Nn + n);
            s_next = sidx[ptc];
#pragma unroll
            for (int i = 0; i < 16; i++) fn[i] = xp[i * Nn];
        }

        // ---- stage current tile: half-pack by s&1, slot-swizzled STS.128 ----
        const bool lo = (s_cur & 1) == 0;
        const int  sb = (s_cur >> 1) & 1;
#pragma unroll
        for (int cc = 0; cc < 4; cc++) {
            unsigned v0, v1, v2, v3;
            v0 = lo ? h2u(__floats2half2_rn(fv[4*cc  ], 0.f)) : h2u(__floats2half2_rn(0.f, fv[4*cc  ]));
            v1 = lo ? h2u(__floats2half2_rn(fv[4*cc+1], 0.f)) : h2u(__floats2half2_rn(0.f, fv[4*cc+1]));
            v2 = lo ? h2u(__floats2half2_rn(fv[4*cc+2], 0.f)) : h2u(__floats2half2_rn(0.f, fv[4*cc+2]));
            v3 = lo ? h2u(__floats2half2_rn(fv[4*cc+3], 0.f)) : h2u(__floats2half2_rn(0.f, fv[4*cc+3]));
            const unsigned slot = ((unsigned)(2 * cc + (l & 1))) ^ ((((unsigned)l >> 1) & 3u) << 1);
            const unsigned addr = sbase + (((unsigned)l >> 1) << 7) + (slot << 4);
            asm volatile("st.shared.v4.b32 [%0], {%1,%2,%3,%4};"
                         :: "r"(addr), "r"(v0), "r"(v1), "r"(v2), "r"(v3));
        }
        __syncwarp();

        // ---- 4 point-groups: ldmatrix + 4 mmas + immediate select/store ----
#pragma unroll
        for (int g = 0; g < 4; g++) {
            const int tt  = l >> 3;
            const int ptv = 8 * g + (l & 7);
            const unsigned slot = ((unsigned)(2 * tt + (ptv & 1))) ^ ((((unsigned)ptv >> 1) & 3u) << 1);
            const unsigned addr = sbase + (((unsigned)ptv >> 1) << 7) + (slot << 4);
            unsigned b0, b1, b2, b3;
            asm volatile("ldmatrix.sync.aligned.m8n8.x4.shared.b16 {%0,%1,%2,%3}, [%4];"
                         : "=r"(b0), "=r"(b1), "=r"(b2), "=r"(b3) : "r"(addr));

            float dl[4] = {br0, br0, br8, br8};
            float dh[4] = {br0, br0, br8, br8};
#pragma unroll
            for (int h = 0; h < 2; h++) {
                float* d = h ? dh : dl;
                asm volatile(
                    "mma.sync.aligned.m16n8k16.row.col.f32.f16.f16.f32 "
                    "{%0,%1,%2,%3}, {%4,%5,%6,%7}, {%8,%9}, {%0,%1,%2,%3};"
                    : "+f"(d[0]), "+f"(d[1]), "+f"(d[2]), "+f"(d[3])
                    : "r"(a[h][0][0]), "r"(a[h][0][1]), "r"(a[h][0][2]), "r"(a[h][0][3]),
                      "r"(b0), "r"(b1));
                asm volatile(
                    "mma.sync.aligned.m16n8k16.row.col.f32.f16.f16.f32 "
                    "{%0,%1,%2,%3}, {%4,%5,%6,%7}, {%8,%9}, {%0,%1,%2,%3};"
                    : "+f"(d[0]), "+f"(d[1]), "+f"(d[2]), "+f"(d[3])
                    : "r"(a[h][1][0]), "r"(a[h][1][1]), "r"(a[h][1][2]), "r"(a[h][1][3]),
                      "r"(b2), "r"(b3));
            }

            // select by s>>1 of the two points this lane holds, store float2
            const int src = 8 * g + 2 * t;
            const int sb0 = __shfl_sync(0xffffffffu, sb, src);
            const int sb1 = __shfl_sync(0xffffffffu, sb, src + 1);
            const float o0 = sb0 ? dh[0] : dl[0];
            const float o1 = sb1 ? dh[1] : dl[1];
            const float o2 = sb0 ? dh[2] : dl[2];
            const float o3 = sb1 ? dh[3] : dl[3];

            const unsigned ptg = wtb + (unsigned)src;
            if (ptg + 1 < P) {
                const unsigned bb = ptg >= Nn ? 1u : 0u;
                const unsigned nn = ptg - bb * Nn;
                float* ob = out + (bb * 16 * Nn + nn);
                *reinterpret_cast<float2*>(ob + (unsigned)r * Nn)       = make_float2(o0, o1);
                *reinterpret_cast<float2*>(ob + (unsigned)(r + 8) * Nn) = make_float2(o2, o3);
            } else if (ptg < P) {
                const unsigned bb = ptg >= Nn ? 1u : 0u;
                const unsigned nn = ptg - bb * Nn;
                float* ob = out + (bb * 16 * Nn + nn);
                ob[(unsigned)r * Nn]       = o0;
                ob[(unsigned)(r + 8) * Nn] = o2;
            }
        }
        __syncwarp();   // ldmatrix reads done before next iter's STS

        // ---- rotate pipeline ----
        wt = wt_next;
        if (wt >= wtiles) break;
        s_cur = s_next;
#pragma unroll
        for (int i = 0; i < 16; i++) fv[i] = fn[i];
    }
}

extern "C" void kernel_launch(void* const* d_in, const int* in_sizes, int n_in,
                              void* d_out, int out_size)
{
    const float* x    = (const float*)d_in[0];   // [B, 16, N]
    const float* Wg   = (const float*)d_in[1];   // [16, 16, 4, 1, 1]
    const float* bias = (const float*)d_in[2];   // [16]
    const int*   sidx = (const int*)d_in[3];     // [B, N]

    float* out = (float*)d_out;

    const unsigned P  = (unsigned)in_sizes[3];   // B*N
    const unsigned Nn = P / 2;                   // B = 2

    const unsigned wtiles = (P + 31) / 32;
    unsigned blk = (wtiles + 3) / 4;
    if (blk > 1480) blk = 1480;

    apr_mma3_kernel<<<blk, THREADS>>>(x, Wg, bias, sidx, out, Nn, P);
}